// round 16
// baseline (speedup 1.0000x reference)
#include <cuda_runtime.h>
#include <cuda_fp16.h>
#include <math.h>
#include <stdint.h>

#define BB 2
#define SS 2048
#define DD 1024
#define HH 16
#define DHD 64
#define NROW (BB*SS)
#define RA 32
#define HR 512
#define HR3 1536
#define R_OUT 512
#define II 4096
#define R_FC 512

// Q pre-scale: (1/sqrt(64)) * log2(e)
#define QSCALE 0.18033688011112042f

__device__ float g_h[NROW*DD];

__device__ __align__(1024) __half g_R16[NROW*HR3];
__device__ __align__(1024) __half g_Q16[NROW*DD];
__device__ __align__(1024) __half g_K16[NROW*DD];
__device__ __align__(1024) __half g_V16[NROW*DD];

__device__ __align__(1024) __half g_A16[NROW*DD];
__device__ __align__(1024) __half g_C16[NROW*II];

__device__ __align__(1024) __half g_Wqkv[HR3*DD];
__device__ __align__(1024) __half g_Wov [DD*R_OUT];
__device__ __align__(1024) __half g_WouN[DD*R_OUT];   // out_U plain fp16 [DD, R_OUT]
__device__ __align__(1024) __half g_Wcomb[DD*DD];     // (out_U@out_V)^T in [N,K]
__device__ __align__(1024) __half g_Wf1u[R_FC*DD];
__device__ __align__(1024) __half g_Wf1v[II*R_FC];
__device__ __align__(1024) __half g_Wf2u[R_FC*II];
__device__ __align__(1024) __half g_Wf2v[DD*R_FC];

#define GDC_WAIT() asm volatile("griddepcontrol.wait;" ::: "memory")

__device__ __forceinline__ uint32_t smem_u32(const void* p) {
    uint32_t a;
    asm("{ .reg .u64 t; cvta.to.shared.u64 t, %1; cvt.u32.u64 %0, t; }" : "=r"(a) : "l"(p));
    return a;
}
__device__ __forceinline__ void cpa16(uint32_t dst, const void* src) {
    asm volatile("cp.async.cg.shared.global [%0], [%1], 16;" :: "r"(dst), "l"(src) : "memory");
}
#define CP_COMMIT() asm volatile("cp.async.commit_group;" ::: "memory")
#define CP_WAIT(n)  asm volatile("cp.async.wait_group %0;" :: "n"(n) : "memory")

__device__ __forceinline__ void mma16816(float* c, uint32_t a0, uint32_t a1, uint32_t a2,
                                         uint32_t a3, uint32_t b0, uint32_t b1) {
    asm volatile(
        "mma.sync.aligned.m16n8k16.row.col.f32.f16.f16.f32 "
        "{%0,%1,%2,%3}, {%4,%5,%6,%7}, {%8,%9}, {%0,%1,%2,%3};"
        : "+f"(c[0]), "+f"(c[1]), "+f"(c[2]), "+f"(c[3])
        : "r"(a0), "r"(a1), "r"(a2), "r"(a3), "r"(b0), "r"(b1));
}
__device__ __forceinline__ void ldmx4(uint32_t& r0, uint32_t& r1, uint32_t& r2,
                                      uint32_t& r3, uint32_t addr) {
    asm volatile("ldmatrix.sync.aligned.m8n8.x4.shared.b16 {%0,%1,%2,%3}, [%4];"
                 : "=r"(r0), "=r"(r1), "=r"(r2), "=r"(r3) : "r"(addr));
}
__device__ __forceinline__ void ldmx4t(uint32_t& r0, uint32_t& r1, uint32_t& r2,
                                       uint32_t& r3, uint32_t addr) {
    asm volatile("ldmatrix.sync.aligned.m8n8.x4.trans.shared.b16 {%0,%1,%2,%3}, [%4];"
                 : "=r"(r0), "=r"(r1), "=r"(r2), "=r"(r3) : "r"(addr));
}
__device__ __forceinline__ uint32_t packh(float a, float b) {
    __half2 t = __float22half2_rn(make_float2(a, b));
    return *(uint32_t*)&t;
}
__device__ __forceinline__ float ex2(float x) {
    float y;
    asm("ex2.approx.f32 %0, %1;" : "=f"(y) : "f"(x));
    return y;
}

__device__ __forceinline__ void ln_body(const float* __restrict__ in,
                                        __half* __restrict__ out,
                                        const float* __restrict__ gw,
                                        const float* __restrict__ bw,
                                        int row, int tid,
                                        float* red, float* stat) {
    const float4* x4 = (const float4*)(in + (size_t)row * DD);
    float4 v = x4[tid];
    float s = v.x + v.y + v.z + v.w;
    #pragma unroll
    for (int o = 16; o; o >>= 1) s += __shfl_xor_sync(0xffffffffu, s, o);
    if ((tid & 31) == 0) red[tid >> 5] = s;
    __syncthreads();
    if (tid < 32) {
        float t = (tid < 8) ? red[tid] : 0.f;
        #pragma unroll
        for (int o = 4; o; o >>= 1) t += __shfl_xor_sync(0xffffffffu, t, o);
        if (tid == 0) stat[0] = t * (1.0f / DD);
    }
    __syncthreads();
    float mu = stat[0];
    float a = v.x - mu, b = v.y - mu, c = v.z - mu, d = v.w - mu;
    float s2 = a*a + b*b + c*c + d*d;
    #pragma unroll
    for (int o = 16; o; o >>= 1) s2 += __shfl_xor_sync(0xffffffffu, s2, o);
    if ((tid & 31) == 0) red[tid >> 5] = s2;
    __syncthreads();
    if (tid < 32) {
        float t = (tid < 8) ? red[tid] : 0.f;
        #pragma unroll
        for (int o = 4; o; o >>= 1) t += __shfl_xor_sync(0xffffffffu, t, o);
        if (tid == 0) stat[1] = rsqrtf(t * (1.0f / DD) + 1e-5f);
    }
    __syncthreads();
    float rs = stat[1];
    float4 g4 = ((const float4*)gw)[tid];
    float4 b4 = ((const float4*)bw)[tid];
    size_t base = (size_t)row * DD + tid * 4;
    *(uint32_t*)(out + base)     = packh(a*rs*g4.x + b4.x, b*rs*g4.y + b4.y);
    *(uint32_t*)(out + base + 2) = packh(c*rs*g4.z + b4.z, d*rs*g4.w + b4.w);
}

// weight transposes + plain out_U copy + LN1 in ONE launch
// [0,7680): transpose tiles ; [7680,8192): out_U plain fp16 ; [8192,+NROW): LN1
__global__ void convAll(const float* __restrict__ q_U, const float* __restrict__ k_U,
                        const float* __restrict__ v_U, const float* __restrict__ out_U,
                        const float* __restrict__ out_V, const float* __restrict__ fc1_U,
                        const float* __restrict__ fc1_V, const float* __restrict__ fc2_U,
                        const float* __restrict__ fc2_V,
                        __half* Wqkv, __half* Wov, __half* WouN, __half* Wf1u,
                        __half* Wf1v, __half* Wf2u, __half* Wf2v,
                        const float* __restrict__ hidden, __half* __restrict__ A16,
                        const float* __restrict__ ln1_g, const float* __restrict__ ln1_b) {
    GDC_WAIT();
    __shared__ float t[32][33];
    __shared__ float red[8];
    __shared__ float stat[2];
    int bid = blockIdx.x;
    int tx = threadIdx.x, ty = threadIdx.y;
    if (bid >= 8192) {
        ln_body(hidden, A16, ln1_g, ln1_b, bid - 8192, ty * 32 + tx, red, stat);
        return;
    }
    if (bid >= 7680) {
        // plain convert of out_U [DD, R_OUT] -> fp16, no transpose
        int local = bid - 7680;
        int nx = R_OUT >> 5;
        int n0 = (local % nx) << 5, k0 = (local / nx) << 5;
        #pragma unroll
        for (int i = 0; i < 4; i++) {
            int row = k0 + ty + 8*i;
            WouN[(size_t)row * R_OUT + n0 + tx] =
                __float2half(out_U[(size_t)row * R_OUT + n0 + tx]);
        }
        return;
    }
    const float* src; __half* dst; int K, N, local;
    if (bid < 1536) {
        int s = bid >> 9; local = bid & 511;
        src = (s == 0) ? q_U : (s == 1) ? k_U : v_U;
        dst = Wqkv + (size_t)s * HR * DD; K = DD; N = HR;
    } else if (bid < 2048) { local = bid - 1536; src = out_V; dst = Wov;  K = R_OUT; N = DD; }
    else if (bid < 2560)   { local = bid - 2048; src = fc1_U; dst = Wf1u; K = DD;    N = R_FC; }
    else if (bid < 4608)   { local = bid - 2560; src = fc1_V; dst = Wf1v; K = R_FC;  N = II; }
    else if (bid < 6656)   { local = bid - 4608; src = fc2_U; dst = Wf2u; K = II;    N = R_FC; }
    else if (bid < 7168)   { local = bid - 6656; src = fc2_V; dst = Wf2v; K = R_FC;  N = DD; }
    else                   { local = bid - 7168; src = fc1_U; dst = Wf1u; K = DD;    N = R_FC;
                             local &= 511; }  // (padding tiles redo fc1_U harmlessly)
    int nx = N >> 5;
    int n0 = (local % nx) << 5, k0 = (local / nx) << 5;

    #pragma unroll
    for (int i = 0; i < 4; i++)
        t[ty + 8*i][tx] = src[(size_t)(k0 + ty + 8*i) * N + n0 + tx];
    __syncthreads();
    #pragma unroll
    for (int i = 0; i < 4; i++)
        dst[(size_t)(n0 + ty + 8*i) * K + k0 + tx] = __float2half(t[tx][ty + 8*i]);
}

__global__ void ln_half(const float* __restrict__ in, __half* __restrict__ out,
                        const float* __restrict__ gw, const float* __restrict__ bw) {
    GDC_WAIT();
    __shared__ float red[8];
    __shared__ float stat[2];
    ln_body(in, out, gw, bw, blockIdx.x, threadIdx.x, red, stat);
}

#define PAD_W 72
#define MAT_B (128*PAD_W*2)
#define STG_B (2*MAT_B)
#define NSTG 3
#define GM_SMEM (NSTG*STG_B)

__device__ __forceinline__ void copy_stage(uint32_t sst,
        const __half* __restrict__ Ap, const __half* __restrict__ Bp,
        int K, int k0, int tid) {
    #pragma unroll
    for (int it = 0; it < 4; it++) {
        int i = tid + it * 256;
        int row = i >> 3, q = i & 7;
        size_t go = (size_t)row * K + k0 + q * 8;
        uint32_t so = (uint32_t)(row * PAD_W + q * 8) * 2;
        cpa16(sst + so,         Ap + go);
        cpa16(sst + MAT_B + so, Bp + go);
    }
}

template<int EPI, int OUT>
__global__ void __launch_bounds__(256, 2)
gemm_mma(const __half* __restrict__ A, const __half* __restrict__ B,
         float* __restrict__ C, __half* __restrict__ O16,
         const float* __restrict__ bias, const float* __restrict__ res,
         int M, int N, int K) {
    GDC_WAIT();
    extern __shared__ char smem_raw[];
    uint32_t sbase = smem_u32(smem_raw);
    int tid = threadIdx.x;
    int wid = tid >> 5, lane = tid & 31;
    int wm = wid >> 2, wn = wid & 3;
    int g = lane >> 2, i4 = lane & 3;
    int bm = blockIdx.y * 128, bn = blockIdx.x * 128;

    const __half* Ap = A + (size_t)bm * K;
    const __half* Bp = B + (size_t)bn * K;

    float acc[4][4][4];
    #pragma unroll
    for (int a = 0; a < 4; a++)
        #pragma unroll
        for (int b = 0; b < 4; b++)
            #pragma unroll
            for (int c = 0; c < 4; c++) acc[a][b][c] = 0.f;

    int arow = wm * 64 + (lane & 15);
    int acol0 = (lane >> 4) * 8;
    int brow = wn * 32 + (lane & 7) + ((lane >> 4) << 3);
    int bcol0 = ((lane >> 3) & 1) * 8;

    int NC = K >> 6;
    copy_stage(sbase, Ap, Bp, K, 0, tid);
    CP_COMMIT();
    copy_stage(sbase + STG_B, Ap, Bp, K, 64, tid);
    CP_COMMIT();

    for (int c = 0; c < NC; c++) {
        if (c + 1 < NC) { CP_WAIT(1); } else { CP_WAIT(0); }
        __syncthreads();
        if (c + 2 < NC) {
            copy_stage(sbase + (uint32_t)((c + 2) % NSTG) * STG_B, Ap, Bp, K, (c + 2) << 6, tid);
            CP_COMMIT();
        }

        uint32_t st = sbase + (uint32_t)(c % NSTG) * STG_B;
        uint32_t stA = st, stB = st + MAT_B;

        #pragma unroll
        for (int ks = 0; ks < 4; ks++) {
            uint32_t bf[4][2];
            #pragma unroll
            for (int nip = 0; nip < 2; nip++) {
                uint32_t addr = stB + (uint32_t)((brow + nip * 16) * PAD_W
                                                 + ks * 16 + bcol0) * 2;
                ldmx4(bf[2*nip][0], bf[2*nip][1], bf[2*nip+1][0], bf[2*nip+1][1], addr);
            }
            #pragma unroll
            for (int mi = 0; mi < 4; mi++) {
                uint32_t addr = stA + (uint32_t)((arow + mi * 16) * PAD_W
                                                 + ks * 16 + acol0) * 2;
                uint32_t a0, a1, a2, a3;
                ldmx4(a0, a1, a2, a3, addr);
                #pragma unroll
                for (int ni = 0; ni < 4; ni++)
                    mma16816(acc[mi][ni], a0, a1, a2, a3, bf[ni][0], bf[ni][1]);
            }
        }
    }

    #pragma unroll
    for (int mi = 0; mi < 4; mi++) {
        int row0 = bm + wm * 64 + mi * 16 + g;
        #pragma unroll
        for (int ni = 0; ni < 4; ni++) {
            int col = bn + wn * 32 + ni * 8 + i4 * 2;
            float v[4];
            v[0] = acc[mi][ni][0]; v[1] = acc[mi][ni][1];
            v[2] = acc[mi][ni][2]; v[3] = acc[mi][ni][3];
            if (EPI != 0) {
                float b0 = bias[col], b1 = bias[col + 1];
                v[0] += b0; v[1] += b1; v[2] += b0; v[3] += b1;
            }
            if (EPI == 2) {
                #pragma unroll
                for (int t = 0; t < 4; t++)
                    v[t] = 0.5f * v[t] * (1.0f + erff(v[t] * 0.70710678118654752f));
            }
            if (EPI == 1) {
                const float* r0 = res + (size_t)row0 * N + col;
                const float* r1 = r0 + 8 * (size_t)N;
                v[0] += r0[0]; v[1] += r0[1]; v[2] += r1[0]; v[3] += r1[1];
            }
            if (OUT == 0) {
                float* p0 = C + (size_t)row0 * N + col;
                float* p1 = p0 + 8 * (size_t)N;
                *(float2*)p0 = make_float2(v[0], v[1]);
                *(float2*)p1 = make_float2(v[2], v[3]);
            } else {
                size_t o0 = (size_t)row0 * N + col;
                size_t o1 = o0 + 8 * (size_t)N;
                *(uint32_t*)(O16 + o0) = packh(v[0], v[1]);
                *(uint32_t*)(O16 + o1) = packh(v[2], v[3]);
            }
        }
    }
}

#define MATB64 (64*PAD_W*2)
#define STG64 (MAT_B + MATB64)
#define GM64_SMEM (NSTG*STG64)

__device__ __forceinline__ void copy_stage64(uint32_t sst,
        const __half* __restrict__ Ap, const __half* __restrict__ Bp,
        int K, int k0, int tid) {
    #pragma unroll
    for (int it = 0; it < 4; it++) {
        int i = tid + it * 256;
        int row = i >> 3, q = i & 7;
        cpa16(sst + (uint32_t)(row * PAD_W + q * 8) * 2,
              Ap + (size_t)row * K + k0 + q * 8);
    }
    #pragma unroll
    for (int it = 0; it < 2; it++) {
        int i = tid + it * 256;
        int row = i >> 3, q = i & 7;
        cpa16(sst + MAT_B + (uint32_t)(row * PAD_W + q * 8) * 2,
              Bp + (size_t)row * K + k0 + q * 8);
    }
}

template<int OUT>
__global__ void __launch_bounds__(256, 2)
gemm_mma64(const __half* __restrict__ A, const __half* __restrict__ B,
           float* __restrict__ C, __half* __restrict__ O16,
           int M, int N, int K) {
    GDC_WAIT();
    extern __shared__ char smem_raw[];
    uint32_t sbase = smem_u32(smem_raw);
    int tid = threadIdx.x;
    int wid = tid >> 5, lane = tid & 31;
    int wm = wid >> 1, wn = wid & 1;
    int g = lane >> 2, i4 = lane & 3;
    int bm = blockIdx.y * 128, bn = blockIdx.x * 64;

    const __half* Ap = A + (size_t)bm * K;
    const __half* Bp = B + (size_t)bn * K;

    float acc[2][4][4];
    #pragma unroll
    for (int a = 0; a < 2; a++)
        #pragma unroll
        for (int b = 0; b < 4; b++)
            #pragma unroll
            for (int c = 0; c < 4; c++) acc[a][b][c] = 0.f;

    int arow = wm * 32 + (lane & 15);
    int acol0 = (lane >> 4) * 8;
    int brow = wn * 32 + (lane & 7) + ((lane >> 4) << 3);
    int bcol0 = ((lane >> 3) & 1) * 8;

    int NC = K >> 6;
    copy_stage64(sbase, Ap, Bp, K, 0, tid);
    CP_COMMIT();
    copy_stage64(sbase + STG64, Ap, Bp, K, 64, tid);
    CP_COMMIT();

    for (int c = 0; c < NC; c++) {
        if (c + 1 < NC) { CP_WAIT(1); } else { CP_WAIT(0); }
        __syncthreads();
        if (c + 2 < NC) {
            copy_stage64(sbase + (uint32_t)((c + 2) % NSTG) * STG64, Ap, Bp, K, (c + 2) << 6, tid);
            CP_COMMIT();
        }

        uint32_t st = sbase + (uint32_t)(c % NSTG) * STG64;
        uint32_t stA = st, stB = st + MAT_B;

        #pragma unroll
        for (int ks = 0; ks < 4; ks++) {
            uint32_t bf[4][2];
            #pragma unroll
            for (int nip = 0; nip < 2; nip++) {
                uint32_t addr = stB + (uint32_t)((brow + nip * 16) * PAD_W
                                                 + ks * 16 + bcol0) * 2;
                ldmx4(bf[2*nip][0], bf[2*nip][1], bf[2*nip+1][0], bf[2*nip+1][1], addr);
            }
            #pragma unroll
            for (int mi = 0; mi < 2; mi++) {
                uint32_t addr = stA + (uint32_t)((arow + mi * 16) * PAD_W
                                                 + ks * 16 + acol0) * 2;
                uint32_t a0, a1, a2, a3;
                ldmx4(a0, a1, a2, a3, addr);
                #pragma unroll
                for (int ni = 0; ni < 4; ni++)
                    mma16816(acc[mi][ni], a0, a1, a2, a3, bf[ni][0], bf[ni][1]);
            }
        }
    }

    #pragma unroll
    for (int mi = 0; mi < 2; mi++) {
        int row0 = bm + wm * 32 + mi * 16 + g;
        #pragma unroll
        for (int ni = 0; ni < 4; ni++) {
            int col = bn + wn * 32 + ni * 8 + i4 * 2;
            float v[4];
            v[0] = acc[mi][ni][0]; v[1] = acc[mi][ni][1];
            v[2] = acc[mi][ni][2]; v[3] = acc[mi][ni][3];
            if (OUT == 0) {
                float* p0 = C + (size_t)row0 * N + col;
                float* p1 = p0 + 8 * (size_t)N;
                *(float2*)p0 = make_float2(v[0], v[1]);
                *(float2*)p1 = make_float2(v[2], v[3]);
            } else {
                size_t o0 = (size_t)row0 * N + col;
                size_t o1 = o0 + 8 * (size_t)N;
                *(uint32_t*)(O16 + o0) = packh(v[0], v[1]);
                *(uint32_t*)(O16 + o1) = packh(v[2], v[3]);
            }
        }
    }
}

__global__ void __launch_bounds__(256)
expand3(const __half* __restrict__ Xr,
        const float* __restrict__ qV, const float* __restrict__ kV,
        const float* __restrict__ vV, const float* __restrict__ qb,
        const float* __restrict__ kb, const float* __restrict__ vb,
        __half* __restrict__ Qo, __half* __restrict__ Ko,
        __half* __restrict__ Vo) {
    GDC_WAIT();
    int which = blockIdx.z;
    const float* Vh = (which == 0) ? qV : (which == 1) ? kV : vV;
    const float* bias = (which == 0) ? qb : (which == 1) ? kb : vb;
    __half* out = (which == 0) ? Qo : (which == 1) ? Ko : Vo;
    float oscale = (which == 0) ? QSCALE : 1.0f;

    int bh = blockIdx.y;
    int b  = bh >> 4;
    int h  = bh & 15;
    int s0 = blockIdx.x * 256;

    __shared__ float Vs[RA][DHD];
    __shared__ float Xs[2][64][36];

    int tid = threadIdx.x;
    int lane = tid & 31, w = tid >> 5;

    const float4* vp4 = (const float4*)(Vh + (size_t)h * RA * DHD);
    ((float4*)Vs)[tid]       = vp4[tid];
    ((float4*)Vs)[tid + 256] = vp4[tid + 256];

    size_t xbase = (size_t)(b * SS + s0) * HR3 + (size_t)which * HR + h * RA;
    int xrow = tid >> 2, xq = tid & 3;

    uint4 xv = *(const uint4*)(Xr + xbase + (size_t)xrow * HR3 + xq * 8);
    {
        __half2* hp = (__half2*)&xv;
        float2 f0 = __half22float2(hp[0]), f1 = __half22float2(hp[1]);
        float2 f2 = __half22float2(hp[2]), f3 = __half22float2(hp[3]);
        float* d = &Xs[0][xrow][xq * 8];
        d[0]=f0.x; d[1]=f0.y; d[2]=f1.x; d[3]=f1.y;
        d[4]=f2.x; d[5]=f2.y; d[6]=f3.x; d[7]=f3.y;
    }
    __syncthreads();

    int e2 = lane * 2;
    float2 vcol[RA];
    #pragma unroll
    for (int r = 0; r < RA; r++)
        vcol[r] = make_float2(Vs[r][e2], Vs[r][e2 + 1]);
    float bb0 = bias[h * DHD + e2];
    float bb1 = bias[h * DHD + e2 + 1];

    #pragma unroll
    for (int t = 0; t < 4; t++) {
        if (t < 3)
            xv = *(const uint4*)(Xr + xbase + (size_t)((t + 1) * 64 + xrow) * HR3 + xq * 8);
        #pragma unroll
        for (int k = 0; k < 8; k++) {
            int row = w + k * 8;
            float a0 = bb0, a1 = bb1;
            const float4* xp = (const float4*)&Xs[t & 1][row][0];
            #pragma unroll
            for (int r4 = 0; r4 < 8; r4++) {
                float4 x = xp[r4];
                a0 = fmaf(x.x, vcol[4*r4].x,   a0); a1 = fmaf(x.x, vcol[4*r4].y,   a1);
                a0 = fmaf(x.y, vcol[4*r4+1].x, a0); a1 = fmaf(x.y, vcol[4*r4+1].y, a1);
                a0 = fmaf(x.z, vcol[4*r4+2].x, a0); a1 = fmaf(x.z, vcol[4*r4+2].y, a1);
                a0 = fmaf(x.w, vcol[4*r4+3].x, a0); a1 = fmaf(x.w, vcol[4*r4+3].y, a1);
            }
            a0 *= oscale; a1 *= oscale;
            size_t oidx = ((size_t)bh * SS + s0 + t * 64 + row) * DHD + e2;
            *(uint32_t*)(out + oidx) = packh(a0, a1);
        }
        if (t < 3) {
            __half2* hp = (__half2*)&xv;
            float2 f0 = __half22float2(hp[0]), f1 = __half22float2(hp[1]);
            float2 f2 = __half22float2(hp[2]), f3 = __half22float2(hp[3]);
            float* d = &Xs[(t + 1) & 1][xrow][xq * 8];
            d[0]=f0.x; d[1]=f0.y; d[2]=f1.x; d[3]=f1.y;
            d[4]=f2.x; d[5]=f2.y; d[6]=f3.x; d[7]=f3.y;
            __syncthreads();
        }
    }
}

// flash attention: paired complementary Q-tiles, fixed-shift exp2 softmax
#define FA_SMEM ((128*72 + 3*2*64*72) * 2)
__global__ void __launch_bounds__(256, 2)
flash_mma(const __half* __restrict__ Qg_, const __half* __restrict__ Kg_,
          const __half* __restrict__ Vg_, __half* __restrict__ O16) {
    GDC_WAIT();
    extern __shared__ char fsm[];
    uint32_t sQ = smem_u32(fsm);
    uint32_t sKV = sQ + 128*72*2;
    const uint32_t VOFF = 64*72*2;
    const uint32_t STGB = 2*VOFF;
    int bh = blockIdx.y;
    int b = bh >> 4, h = bh & 15;
    int tid = threadIdx.x, wid = tid >> 5, lane = tid & 31;
    int g = lane >> 2, i4 = lane & 3;
    const __half* Kg = Kg_ + (size_t)bh * SS * DHD;
    const __half* Vg = Vg_ + (size_t)bh * SS * DHD;
    int kbrow = (lane & 7) + ((lane >> 4) << 3);
    int kbcol = ((lane >> 3) & 1) * 8;
    int ntile = (int)gridDim.x * 2;

    #pragma unroll
    for (int half = 0; half < 2; half++) {
        int tileIdx = half ? (int)blockIdx.x : (ntile - 1 - (int)blockIdx.x);
        int m0 = tileIdx * 128;
        const __half* Qg = Qg_ + ((size_t)bh * SS + m0) * DHD;
        int NT = m0/64 + 2;

        if (half) __syncthreads();

        #pragma unroll
        for (int it = 0; it < 4; it++) {
            int i = tid + it * 256; int r = i >> 3, q = i & 7;
            cpa16(sQ + (uint32_t)(r*72 + q*8)*2, Qg + (size_t)r*DHD + q*8);
        }
        #pragma unroll
        for (int it = 0; it < 2; it++) {
            int i = tid + it * 256; int r = i >> 3, q = i & 7;
            uint32_t so = (uint32_t)(r*72 + q*8)*2;
            cpa16(sKV + so,        Kg + (size_t)r*DHD + q*8);
            cpa16(sKV + VOFF + so, Vg + (size_t)r*DHD + q*8);
        }
        CP_COMMIT();
        {
            const __half* Kp = Kg + (size_t)64*DHD;
            const __half* Vp = Vg + (size_t)64*DHD;
            #pragma unroll
            for (int it = 0; it < 2; it++) {
                int i = tid + it * 256; int r = i >> 3, q = i & 7;
                uint32_t so = (uint32_t)(r*72 + q*8)*2;
                cpa16(sKV + STGB + so,        Kp + (size_t)r*DHD + q*8);
                cpa16(sKV + STGB + VOFF + so, Vp + (size_t)r*DHD + q*8);
            }
            CP_COMMIT();
        }
        CP_WAIT(1);
        __syncthreads();

        uint32_t qf[4][4];
        {
            uint32_t base = sQ + (uint32_t)((wid*16 + (lane & 15))*72 + (lane >> 4)*8)*2;
            #pragma unroll
            for (int t = 0; t < 4; t++)
                ldmx4(qf[t][0], qf[t][1], qf[t][2], qf[t][3], base + (uint32_t)(t*16)*2);
        }

        float o[8][4];
        #pragma unroll
        for (int u = 0; u < 8; u++) { o[u][0]=o[u][1]=o[u][2]=o[u][3]=0.f; }
        float l0f = 0.f, l1f = 0.f;

        for (int ti = 0; ti < NT; ti++) {
            if (ti > 0) {
                if (ti + 1 < NT) { CP_WAIT(1); } else { CP_WAIT(0); }
                __syncthreads();
            }
            if (ti + 2 < NT) {
                const __half* Kp = Kg + (size_t)(ti+2)*64*DHD;
                const __half* Vp = Vg + (size_t)(ti+2)*64*DHD;
                uint32_t sst = sKV + (uint32_t)((ti+2) % 3) * STGB;
                #pragma unroll
                for (int it = 0; it < 2; it++) {
                    int i = tid + it * 256; int r = i >> 3, q = i & 7;
                    uint32_t so = (uint32_t)(r*72 + q*8)*2;
                    cpa16(sst + so,        Kp + (size_t)r*DHD + q*8);
                    cpa16(sst + VOFF + so, Vp + (size_t)r*DHD + q*8);
                }
                CP_COMMIT();
            }
            uint32_t sK = sKV + (uint32_t)(ti % 3) * STGB;
            uint32_t sV = sK + VOFF;

            float s[8][4];
            #pragma unroll
            for (int nt = 0; nt < 8; nt++) { s[nt][0]=s[nt][1]=s[nt][2]=s[nt][3]=0.f; }
            #pragma unroll
            for (int t = 0; t < 4; t++) {
                #pragma unroll
                for (int nip = 0; nip < 4; nip++) {
                    uint32_t addr = sK + (uint32_t)((nip*16 + kbrow)*72 + t*16 + kbcol)*2;
                    uint32_t b0, b1, b2, b3;
                    ldmx4(b0, b1, b2, b3, addr);
                    mma16816(s[2*nip],   qf[t][0], qf[t][1], qf[t][2], qf[t][3], b0, b1);
                    mma16816(s[2*nip+1], qf[t][0], qf[t][1], qf[t][2], qf[t][3], b2, b3);
                }
            }

            bool diag = (ti >= NT - 2);
            if (diag) {
                int grow0 = m0 + wid*16 + g;
                int grow1 = grow0 + 8;
                #pragma unroll
                for (int nt = 0; nt < 8; nt++) {
                    int c0 = ti*64 + nt*8 + 2*i4;
                    if (c0     > grow0) s[nt][0] = -1e30f;
                    if (c0 + 1 > grow0) s[nt][1] = -1e30f;
                    if (c0     > grow1) s[nt][2] = -1e30f;
                    if (c0 + 1 > grow1) s[nt][3] = -1e30f;
                }
            }
            #pragma unroll
            for (int nt = 0; nt < 8; nt++) {
                float p0 = ex2(s[nt][0]);
                float p1 = ex2(s[nt][1]);
                float p2 = ex2(s[nt][2]);
                float p3 = ex2(s[nt][3]);
                s[nt][0]=p0; s[nt][1]=p1; s[nt][2]=p2; s[nt][3]=p3;
                l0f += p0 + p1; l1f += p2 + p3;
            }

            #pragma unroll
            for (int t = 0; t < 4; t++) {
                uint32_t pa0 = packh(s[2*t][0],   s[2*t][1]);
                uint32_t pa1 = packh(s[2*t][2],   s[2*t][3]);
                uint32_t pa2 = packh(s[2*t+1][0], s[2*t+1][1]);
                uint32_t pa3 = packh(s[2*t+1][2], s[2*t+1][3]);
                #pragma unroll
                for (int u = 0; u < 4; u++) {
                    uint32_t addr = sV + (uint32_t)((t*16 + (lane & 15))*36
                                                    + u*8 + ((lane >> 4) << 2))*4;
                    uint32_t r0, r1, r2, r3;
                    ldmx4t(r0, r1, r2, r3, addr);
                    mma16816(o[2*u],     pa0, pa1, pa2, pa3, r0, r1);
                    mma16816(o[2*u + 1], pa0, pa1, pa2, pa3, r2, r3);
                }
            }
        }

        l0f += __shfl_xor_sync(0xffffffffu, l0f, 1);
        l0f += __shfl_xor_sync(0xffffffffu, l0f, 2);
        l1f += __shfl_xor_sync(0xffffffffu, l1f, 1);
        l1f += __shfl_xor_sync(0xffffffffu, l1f, 2);

        float inv0 = 1.f / l0f, inv1 = 1.f / l1f;
        int r0g = m0 + wid*16 + g;
        size_t base0 = ((size_t)b * SS + r0g) * DD + h * DHD;
        size_t base1 = base0 + 8 * (size_t)DD;
        #pragma unroll
        for (int u = 0; u < 8; u++) {
            int col = u*8 + 2*i4;
            *(uint32_t*)(O16 + base0 + col) = packh(o[u][0]*inv0, o[u][1]*inv0);
            *(uint32_t*)(O16 + base1 + col) = packh(o[u][2]*inv1, o[u][3]*inv1);
        }
    }
}

template<typename F, typename... Args>
static inline void launch_pdl(F kern, dim3 grid, dim3 block, size_t smem, Args... args) {
    cudaLaunchConfig_t cfg = {};
    cfg.gridDim = grid;
    cfg.blockDim = block;
    cfg.dynamicSmemBytes = smem;
    cfg.stream = 0;
    cudaLaunchAttribute attr[1];
    attr[0].id = cudaLaunchAttributeProgrammaticStreamSerialization;
    attr[0].val.programmaticStreamSerializationAllowed = 1;
    cfg.attrs = attr;
    cfg.numAttrs = 1;
    cudaLaunchKernelEx(&cfg, kern, args...);
}

extern "C" void kernel_launch(void* const* d_in, const int* in_sizes, int n_in,
                              void* d_out, int out_size) {
    const float* hidden = (const float*)d_in[0];
    const float* ln1_g  = (const float*)d_in[1];
    const float* ln1_b  = (const float*)d_in[2];
    const float* ln2_g  = (const float*)d_in[3];
    const float* ln2_b  = (const float*)d_in[4];
    const float* q_U = (const float*)d_in[5];
    const float* q_V = (const float*)d_in[6];
    const float* q_b = (const float*)d_in[7];
    const float* k_U = (const float*)d_in[8];
    const float* k_V = (const float*)d_in[9];
    const float* k_b = (const float*)d_in[10];
    const float* v_U = (const float*)d_in[11];
    const float* v_V = (const float*)d_in[12];
    const float* v_b = (const float*)d_in[13];
    const float* out_U = (const float*)d_in[14];
    const float* out_V = (const float*)d_in[15];
    const float* out_b = (const float*)d_in[16];
    const float* fc1_U = (const float*)d_in[17];
    const float* fc1_V = (const float*)d_in[18];
    const float* fc1_b = (const float*)d_in[19];
    const float* fc2_U = (const float*)d_in[20];
    const float* fc2_V = (const float*)d_in[21];
    const float* fc2_b = (const float*)d_in[22];
    float* out = (float*)d_out;

    float* hb;
    __half *A16, *C16, *R16, *Q16, *K16, *V16;
    __half *Wqkv, *Wov, *WouN, *Wcomb, *Wf1u, *Wf1v, *Wf2u, *Wf2v;
    cudaGetSymbolAddress((void**)&hb,   g_h);
    cudaGetSymbolAddress((void**)&A16,  g_A16);
    cudaGetSymbolAddress((void**)&C16,  g_C16);
    cudaGetSymbolAddress((void**)&R16,  g_R16);
    cudaGetSymbolAddress((void**)&Q16,  g_Q16);
    cudaGetSymbolAddress((void**)&K16,  g_K16);
    cudaGetSymbolAddress((void**)&V16,  g_V16);
    cudaGetSymbolAddress((void**)&Wqkv, g_Wqkv);
    cudaGetSymbolAddress((void**)&Wov,  g_Wov);
    cudaGetSymbolAddress((void**)&WouN, g_WouN);
    cudaGetSymbolAddress((void**)&Wcomb, g_Wcomb);
    cudaGetSymbolAddress((void**)&Wf1u, g_Wf1u);
    cudaGetSymbolAddress((void**)&Wf1v, g_Wf1v);
    cudaGetSymbolAddress((void**)&Wf2u, g_Wf2u);
    cudaGetSymbolAddress((void**)&Wf2v, g_Wf2v);

    cudaFuncSetAttribute(gemm_mma<0,1>, cudaFuncAttributeMaxDynamicSharedMemorySize, GM_SMEM);
    cudaFuncSetAttribute(gemm_mma<1,0>, cudaFuncAttributeMaxDynamicSharedMemorySize, GM_SMEM);
    cudaFuncSetAttribute(gemm_mma<2,1>, cudaFuncAttributeMaxDynamicSharedMemorySize, GM_SMEM);
    cudaFuncSetAttribute(gemm_mma64<1>, cudaFuncAttributeMaxDynamicSharedMemorySize, GM64_SMEM);
    cudaFuncSetAttribute(flash_mma, cudaFuncAttributeMaxDynamicSharedMemorySize, FA_SMEM);

    // weight conversions (+ plain out_U fp16) + LN1
    launch_pdl(convAll, dim3(8192 + NROW), dim3(32, 8), (size_t)0,
               q_U, k_U, v_U, out_U, out_V, fc1_U, fc1_V, fc2_U, fc2_V,
               Wqkv, Wov, WouN, Wf1u, Wf1v, Wf2u, Wf2v, hidden, A16, ln1_g, ln1_b);

    // combined out-proj weight: Wcomb[n,k] = sum_r out_V[r,n]*out_U[k,r]
    launch_pdl(gemm_mma<0,1>, dim3(DD/128, DD/128), dim3(256), (size_t)GM_SMEM,
               (const __half*)Wov, (const __half*)WouN, (float*)nullptr, Wcomb,
               (const float*)nullptr, (const float*)nullptr, DD, DD, R_OUT);

    // fused qkv rank projection -> fp16 R16
    launch_pdl(gemm_mma<0,1>, dim3(HR3/128, NROW/128), dim3(256), (size_t)GM_SMEM,
               (const __half*)A16, (const __half*)Wqkv, (float*)nullptr, R16,
               (const float*)nullptr, (const float*)nullptr, NROW, HR3, DD);

    launch_pdl(expand3, dim3(SS/256, BB*HH, 3), dim3(256), (size_t)0,
               (const __half*)R16, q_V, k_V, v_V, q_b, k_b, v_b, Q16, K16, V16);

    launch_pdl(flash_mma, dim3(SS/256, BB*HH), dim3(256), (size_t)FA_SMEM,
               (const __half*)Q16, (const __half*)K16, (const __half*)V16, C16);

    // single fused out projection + bias + residual
    launch_pdl(gemm_mma<1,0>, dim3(DD/128, NROW/128), dim3(256), (size_t)GM_SMEM,
               (const __half*)C16, (const __half*)Wcomb, hb, (__half*)nullptr,
               out_b, hidden, NROW, DD, DD);

    launch_pdl(ln_half, dim3(NROW), dim3(256), (size_t)0,
               (const float*)hb, C16, ln2_g, ln2_b);

    launch_pdl(gemm_mma64<1>, dim3(R_FC/64, NROW/128), dim3(256), (size_t)GM64_SMEM,
               (const __half*)C16, (const __half*)Wf1u, (float*)nullptr, A16,
               NROW, R_FC, DD);
    launch_pdl(gemm_mma<2,1>, dim3(II/128, NROW/128), dim3(256), (size_t)GM_SMEM,
               (const __half*)A16, (const __half*)Wf1v, (float*)nullptr, C16,
               fc1_b, (const float*)nullptr, NROW, II, R_FC);
    launch_pdl(gemm_mma64<1>, dim3(R_FC/64, NROW/128), dim3(256), (size_t)GM64_SMEM,
               (const __half*)C16, (const __half*)Wf2u, (float*)nullptr, A16,
               NROW, R_FC, II);
    launch_pdl(gemm_mma<1,0>, dim3(DD/128, NROW/128), dim3(256), (size_t)GM_SMEM,
               (const __half*)A16, (const __half*)Wf2v, out, (__half*)nullptr,
               fc2_b, hb, NROW, DD, R_FC);
}

// round 17
// speedup vs baseline: 1.0331x; 1.0331x over previous
#include <cuda_runtime.h>
#include <cuda_fp16.h>
#include <math.h>
#include <stdint.h>

#define BB 2
#define SS 2048
#define DD 1024
#define HH 16
#define DHD 64
#define NROW (BB*SS)
#define RA 32
#define HR 512
#define HR3 1536
#define R_OUT 512
#define II 4096
#define R_FC 512

// Q pre-scale: (1/sqrt(64)) * log2(e)
#define QSCALE 0.18033688011112042f

__device__ float g_h[NROW*DD];

__device__ __align__(1024) __half g_R16[NROW*HR3];
__device__ __align__(1024) __half g_Q16[NROW*DD];
__device__ __align__(1024) __half g_K16[NROW*DD];
__device__ __align__(1024) __half g_V16[NROW*DD];

__device__ __align__(1024) __half g_A16[NROW*DD];
__device__ __align__(1024) __half g_C16[NROW*II];

__device__ __align__(1024) __half g_Wqkv[HR3*DD];
__device__ __align__(1024) __half g_Wou [R_OUT*DD];
__device__ __align__(1024) __half g_Wov [DD*R_OUT];
__device__ __align__(1024) __half g_Wf1u[R_FC*DD];
__device__ __align__(1024) __half g_Wf1v[II*R_FC];
__device__ __align__(1024) __half g_Wf2u[R_FC*II];
__device__ __align__(1024) __half g_Wf2v[DD*R_FC];

#define GDC_WAIT() asm volatile("griddepcontrol.wait;" ::: "memory")

__device__ __forceinline__ uint32_t smem_u32(const void* p) {
    uint32_t a;
    asm("{ .reg .u64 t; cvta.to.shared.u64 t, %1; cvt.u32.u64 %0, t; }" : "=r"(a) : "l"(p));
    return a;
}
__device__ __forceinline__ void cpa16(uint32_t dst, const void* src) {
    asm volatile("cp.async.cg.shared.global [%0], [%1], 16;" :: "r"(dst), "l"(src) : "memory");
}
#define CP_COMMIT() asm volatile("cp.async.commit_group;" ::: "memory")
#define CP_WAIT(n)  asm volatile("cp.async.wait_group %0;" :: "n"(n) : "memory")

__device__ __forceinline__ void mma16816(float* c, uint32_t a0, uint32_t a1, uint32_t a2,
                                         uint32_t a3, uint32_t b0, uint32_t b1) {
    asm volatile(
        "mma.sync.aligned.m16n8k16.row.col.f32.f16.f16.f32 "
        "{%0,%1,%2,%3}, {%4,%5,%6,%7}, {%8,%9}, {%0,%1,%2,%3};"
        : "+f"(c[0]), "+f"(c[1]), "+f"(c[2]), "+f"(c[3])
        : "r"(a0), "r"(a1), "r"(a2), "r"(a3), "r"(b0), "r"(b1));
}
__device__ __forceinline__ void ldmx4(uint32_t& r0, uint32_t& r1, uint32_t& r2,
                                      uint32_t& r3, uint32_t addr) {
    asm volatile("ldmatrix.sync.aligned.m8n8.x4.shared.b16 {%0,%1,%2,%3}, [%4];"
                 : "=r"(r0), "=r"(r1), "=r"(r2), "=r"(r3) : "r"(addr));
}
__device__ __forceinline__ void ldmx4t(uint32_t& r0, uint32_t& r1, uint32_t& r2,
                                       uint32_t& r3, uint32_t addr) {
    asm volatile("ldmatrix.sync.aligned.m8n8.x4.trans.shared.b16 {%0,%1,%2,%3}, [%4];"
                 : "=r"(r0), "=r"(r1), "=r"(r2), "=r"(r3) : "r"(addr));
}
__device__ __forceinline__ uint32_t packh(float a, float b) {
    __half2 t = __float22half2_rn(make_float2(a, b));
    return *(uint32_t*)&t;
}
__device__ __forceinline__ float ex2(float x) {
    float y;
    asm("ex2.approx.f32 %0, %1;" : "=f"(y) : "f"(x));
    return y;
}

__device__ __forceinline__ void ln_body(const float* __restrict__ in,
                                        __half* __restrict__ out,
                                        const float* __restrict__ gw,
                                        const float* __restrict__ bw,
                                        int row, int tid,
                                        float* red, float* stat) {
    const float4* x4 = (const float4*)(in + (size_t)row * DD);
    float4 v = x4[tid];
    float s = v.x + v.y + v.z + v.w;
    #pragma unroll
    for (int o = 16; o; o >>= 1) s += __shfl_xor_sync(0xffffffffu, s, o);
    if ((tid & 31) == 0) red[tid >> 5] = s;
    __syncthreads();
    if (tid < 32) {
        float t = (tid < 8) ? red[tid] : 0.f;
        #pragma unroll
        for (int o = 4; o; o >>= 1) t += __shfl_xor_sync(0xffffffffu, t, o);
        if (tid == 0) stat[0] = t * (1.0f / DD);
    }
    __syncthreads();
    float mu = stat[0];
    float a = v.x - mu, b = v.y - mu, c = v.z - mu, d = v.w - mu;
    float s2 = a*a + b*b + c*c + d*d;
    #pragma unroll
    for (int o = 16; o; o >>= 1) s2 += __shfl_xor_sync(0xffffffffu, s2, o);
    if ((tid & 31) == 0) red[tid >> 5] = s2;
    __syncthreads();
    if (tid < 32) {
        float t = (tid < 8) ? red[tid] : 0.f;
        #pragma unroll
        for (int o = 4; o; o >>= 1) t += __shfl_xor_sync(0xffffffffu, t, o);
        if (tid == 0) stat[1] = rsqrtf(t * (1.0f / DD) + 1e-5f);
    }
    __syncthreads();
    float rs = stat[1];
    float4 g4 = ((const float4*)gw)[tid];
    float4 b4 = ((const float4*)bw)[tid];
    size_t base = (size_t)row * DD + tid * 4;
    *(uint32_t*)(out + base)     = packh(a*rs*g4.x + b4.x, b*rs*g4.y + b4.y);
    *(uint32_t*)(out + base + 2) = packh(c*rs*g4.z + b4.z, d*rs*g4.w + b4.w);
}

// weight transposes + LN1 in ONE launch (round-15 layout)
__global__ void convAll(const float* __restrict__ q_U, const float* __restrict__ k_U,
                        const float* __restrict__ v_U, const float* __restrict__ out_U,
                        const float* __restrict__ out_V, const float* __restrict__ fc1_U,
                        const float* __restrict__ fc1_V, const float* __restrict__ fc2_U,
                        const float* __restrict__ fc2_V,
                        __half* Wqkv, __half* Wou, __half* Wov, __half* Wf1u,
                        __half* Wf1v, __half* Wf2u, __half* Wf2v,
                        const float* __restrict__ hidden, __half* __restrict__ A16,
                        const float* __restrict__ ln1_g, const float* __restrict__ ln1_b) {
    GDC_WAIT();
    __shared__ float t[32][33];
    __shared__ float red[8];
    __shared__ float stat[2];
    int bid = blockIdx.x;
    int tx = threadIdx.x, ty = threadIdx.y;
    if (bid >= 7680) {
        ln_body(hidden, A16, ln1_g, ln1_b, bid - 7680, ty * 32 + tx, red, stat);
        return;
    }
    const float* src; __half* dst; int K, N, local;
    if (bid < 1536) {
        int s = bid >> 9; local = bid & 511;
        src = (s == 0) ? q_U : (s == 1) ? k_U : v_U;
        dst = Wqkv + (size_t)s * HR * DD; K = DD; N = HR;
    } else if (bid < 2048) { local = bid - 1536; src = out_U; dst = Wou;  K = DD;    N = R_OUT; }
    else if (bid < 2560)   { local = bid - 2048; src = out_V; dst = Wov;  K = R_OUT; N = DD; }
    else if (bid < 3072)   { local = bid - 2560; src = fc1_U; dst = Wf1u; K = DD;    N = R_FC; }
    else if (bid < 5120)   { local = bid - 3072; src = fc1_V; dst = Wf1v; K = R_FC;  N = II; }
    else if (bid < 7168)   { local = bid - 5120; src = fc2_U; dst = Wf2u; K = II;    N = R_FC; }
    else                   { local = bid - 7168; src = fc2_V; dst = Wf2v; K = R_FC;  N = DD; }
    int nx = N >> 5;
    int n0 = (local % nx) << 5, k0 = (local / nx) << 5;

    #pragma unroll
    for (int i = 0; i < 4; i++)
        t[ty + 8*i][tx] = src[(size_t)(k0 + ty + 8*i) * N + n0 + tx];
    __syncthreads();
    #pragma unroll
    for (int i = 0; i < 4; i++)
        dst[(size_t)(n0 + ty + 8*i) * K + k0 + tx] = __float2half(t[tx][ty + 8*i]);
}

__global__ void ln_half(const float* __restrict__ in, __half* __restrict__ out,
                        const float* __restrict__ gw, const float* __restrict__ bw) {
    GDC_WAIT();
    __shared__ float red[8];
    __shared__ float stat[2];
    ln_body(in, out, gw, bw, blockIdx.x, threadIdx.x, red, stat);
}

#define PAD_W 72
#define MAT_B (128*PAD_W*2)
#define STG_B (2*MAT_B)
#define NSTG 3
#define GM_SMEM (NSTG*STG_B)

__device__ __forceinline__ void copy_stage(uint32_t sst,
        const __half* __restrict__ Ap, const __half* __restrict__ Bp,
        int K, int k0, int tid) {
    #pragma unroll
    for (int it = 0; it < 4; it++) {
        int i = tid + it * 256;
        int row = i >> 3, q = i & 7;
        size_t go = (size_t)row * K + k0 + q * 8;
        uint32_t so = (uint32_t)(row * PAD_W + q * 8) * 2;
        cpa16(sst + so,         Ap + go);
        cpa16(sst + MAT_B + so, Bp + go);
    }
}

template<int EPI, int OUT>
__global__ void __launch_bounds__(256, 2)
gemm_mma(const __half* __restrict__ A, const __half* __restrict__ B,
         float* __restrict__ C, __half* __restrict__ O16,
         const float* __restrict__ bias, const float* __restrict__ res,
         int M, int N, int K) {
    GDC_WAIT();
    extern __shared__ char smem_raw[];
    uint32_t sbase = smem_u32(smem_raw);
    int tid = threadIdx.x;
    int wid = tid >> 5, lane = tid & 31;
    int wm = wid >> 2, wn = wid & 3;
    int g = lane >> 2, i4 = lane & 3;
    int bm = blockIdx.y * 128, bn = blockIdx.x * 128;

    const __half* Ap = A + (size_t)bm * K;
    const __half* Bp = B + (size_t)bn * K;

    float acc[4][4][4];
    #pragma unroll
    for (int a = 0; a < 4; a++)
        #pragma unroll
        for (int b = 0; b < 4; b++)
            #pragma unroll
            for (int c = 0; c < 4; c++) acc[a][b][c] = 0.f;

    int arow = wm * 64 + (lane & 15);
    int acol0 = (lane >> 4) * 8;
    int brow = wn * 32 + (lane & 7) + ((lane >> 4) << 3);
    int bcol0 = ((lane >> 3) & 1) * 8;

    int NC = K >> 6;
    copy_stage(sbase, Ap, Bp, K, 0, tid);
    CP_COMMIT();
    copy_stage(sbase + STG_B, Ap, Bp, K, 64, tid);
    CP_COMMIT();

    for (int c = 0; c < NC; c++) {
        if (c + 1 < NC) { CP_WAIT(1); } else { CP_WAIT(0); }
        __syncthreads();
        if (c + 2 < NC) {
            copy_stage(sbase + (uint32_t)((c + 2) % NSTG) * STG_B, Ap, Bp, K, (c + 2) << 6, tid);
            CP_COMMIT();
        }

        uint32_t st = sbase + (uint32_t)(c % NSTG) * STG_B;
        uint32_t stA = st, stB = st + MAT_B;

        #pragma unroll
        for (int ks = 0; ks < 4; ks++) {
            uint32_t bf[4][2];
            #pragma unroll
            for (int nip = 0; nip < 2; nip++) {
                uint32_t addr = stB + (uint32_t)((brow + nip * 16) * PAD_W
                                                 + ks * 16 + bcol0) * 2;
                ldmx4(bf[2*nip][0], bf[2*nip][1], bf[2*nip+1][0], bf[2*nip+1][1], addr);
            }
            #pragma unroll
            for (int mi = 0; mi < 4; mi++) {
                uint32_t addr = stA + (uint32_t)((arow + mi * 16) * PAD_W
                                                 + ks * 16 + acol0) * 2;
                uint32_t a0, a1, a2, a3;
                ldmx4(a0, a1, a2, a3, addr);
                #pragma unroll
                for (int ni = 0; ni < 4; ni++)
                    mma16816(acc[mi][ni], a0, a1, a2, a3, bf[ni][0], bf[ni][1]);
            }
        }
    }

    #pragma unroll
    for (int mi = 0; mi < 4; mi++) {
        int row0 = bm + wm * 64 + mi * 16 + g;
        #pragma unroll
        for (int ni = 0; ni < 4; ni++) {
            int col = bn + wn * 32 + ni * 8 + i4 * 2;
            float v[4];
            v[0] = acc[mi][ni][0]; v[1] = acc[mi][ni][1];
            v[2] = acc[mi][ni][2]; v[3] = acc[mi][ni][3];
            if (EPI != 0) {
                float b0 = bias[col], b1 = bias[col + 1];
                v[0] += b0; v[1] += b1; v[2] += b0; v[3] += b1;
            }
            if (EPI == 2) {
                #pragma unroll
                for (int t = 0; t < 4; t++)
                    v[t] = 0.5f * v[t] * (1.0f + erff(v[t] * 0.70710678118654752f));
            }
            if (EPI == 1) {
                const float* r0 = res + (size_t)row0 * N + col;
                const float* r1 = r0 + 8 * (size_t)N;
                v[0] += r0[0]; v[1] += r0[1]; v[2] += r1[0]; v[3] += r1[1];
            }
            if (OUT == 0) {
                float* p0 = C + (size_t)row0 * N + col;
                float* p1 = p0 + 8 * (size_t)N;
                *(float2*)p0 = make_float2(v[0], v[1]);
                *(float2*)p1 = make_float2(v[2], v[3]);
            } else {
                size_t o0 = (size_t)row0 * N + col;
                size_t o1 = o0 + 8 * (size_t)N;
                *(uint32_t*)(O16 + o0) = packh(v[0], v[1]);
                *(uint32_t*)(O16 + o1) = packh(v[2], v[3]);
            }
        }
    }
}

#define MATB64 (64*PAD_W*2)
#define STG64 (MAT_B + MATB64)
#define GM64_SMEM (NSTG*STG64)

__device__ __forceinline__ void copy_stage64(uint32_t sst,
        const __half* __restrict__ Ap, const __half* __restrict__ Bp,
        int K, int k0, int tid) {
    #pragma unroll
    for (int it = 0; it < 4; it++) {
        int i = tid + it * 256;
        int row = i >> 3, q = i & 7;
        cpa16(sst + (uint32_t)(row * PAD_W + q * 8) * 2,
              Ap + (size_t)row * K + k0 + q * 8);
    }
    #pragma unroll
    for (int it = 0; it < 2; it++) {
        int i = tid + it * 256;
        int row = i >> 3, q = i & 7;
        cpa16(sst + MAT_B + (uint32_t)(row * PAD_W + q * 8) * 2,
              Bp + (size_t)row * K + k0 + q * 8);
    }
}

template<int OUT>
__global__ void __launch_bounds__(256, 2)
gemm_mma64(const __half* __restrict__ A, const __half* __restrict__ B,
           float* __restrict__ C, __half* __restrict__ O16,
           int M, int N, int K) {
    GDC_WAIT();
    extern __shared__ char smem_raw[];
    uint32_t sbase = smem_u32(smem_raw);
    int tid = threadIdx.x;
    int wid = tid >> 5, lane = tid & 31;
    int wm = wid >> 1, wn = wid & 1;
    int g = lane >> 2, i4 = lane & 3;
    int bm = blockIdx.y * 128, bn = blockIdx.x * 64;

    const __half* Ap = A + (size_t)bm * K;
    const __half* Bp = B + (size_t)bn * K;

    float acc[2][4][4];
    #pragma unroll
    for (int a = 0; a < 2; a++)
        #pragma unroll
        for (int b = 0; b < 4; b++)
            #pragma unroll
            for (int c = 0; c < 4; c++) acc[a][b][c] = 0.f;

    int arow = wm * 32 + (lane & 15);
    int acol0 = (lane >> 4) * 8;
    int brow = wn * 32 + (lane & 7) + ((lane >> 4) << 3);
    int bcol0 = ((lane >> 3) & 1) * 8;

    int NC = K >> 6;
    copy_stage64(sbase, Ap, Bp, K, 0, tid);
    CP_COMMIT();
    copy_stage64(sbase + STG64, Ap, Bp, K, 64, tid);
    CP_COMMIT();

    for (int c = 0; c < NC; c++) {
        if (c + 1 < NC) { CP_WAIT(1); } else { CP_WAIT(0); }
        __syncthreads();
        if (c + 2 < NC) {
            copy_stage64(sbase + (uint32_t)((c + 2) % NSTG) * STG64, Ap, Bp, K, (c + 2) << 6, tid);
            CP_COMMIT();
        }

        uint32_t st = sbase + (uint32_t)(c % NSTG) * STG64;
        uint32_t stA = st, stB = st + MAT_B;

        #pragma unroll
        for (int ks = 0; ks < 4; ks++) {
            uint32_t bf[4][2];
            #pragma unroll
            for (int nip = 0; nip < 2; nip++) {
                uint32_t addr = stB + (uint32_t)((brow + nip * 16) * PAD_W
                                                 + ks * 16 + bcol0) * 2;
                ldmx4(bf[2*nip][0], bf[2*nip][1], bf[2*nip+1][0], bf[2*nip+1][1], addr);
            }
            #pragma unroll
            for (int mi = 0; mi < 2; mi++) {
                uint32_t addr = stA + (uint32_t)((arow + mi * 16) * PAD_W
                                                 + ks * 16 + acol0) * 2;
                uint32_t a0, a1, a2, a3;
                ldmx4(a0, a1, a2, a3, addr);
                #pragma unroll
                for (int ni = 0; ni < 4; ni++)
                    mma16816(acc[mi][ni], a0, a1, a2, a3, bf[ni][0], bf[ni][1]);
            }
        }
    }

    #pragma unroll
    for (int mi = 0; mi < 2; mi++) {
        int row0 = bm + wm * 32 + mi * 16 + g;
        #pragma unroll
        for (int ni = 0; ni < 4; ni++) {
            int col = bn + wn * 32 + ni * 8 + i4 * 2;
            float v[4];
            v[0] = acc[mi][ni][0]; v[1] = acc[mi][ni][1];
            v[2] = acc[mi][ni][2]; v[3] = acc[mi][ni][3];
            if (OUT == 0) {
                float* p0 = C + (size_t)row0 * N + col;
                float* p1 = p0 + 8 * (size_t)N;
                *(float2*)p0 = make_float2(v[0], v[1]);
                *(float2*)p1 = make_float2(v[2], v[3]);
            } else {
                size_t o0 = (size_t)row0 * N + col;
                size_t o1 = o0 + 8 * (size_t)N;
                *(uint32_t*)(O16 + o0) = packh(v[0], v[1]);
                *(uint32_t*)(O16 + o1) = packh(v[2], v[3]);
            }
        }
    }
}

// expand3 v4: packed half2 inner product (X kept fp16 end-to-end).
// vcolA/vcolB pair consecutive ranks per output column; 32 HFMA2 per row
// computes both output columns; horizontal add + bias in fp32.
__global__ void __launch_bounds__(256)
expand3(const __half* __restrict__ Xr,
        const float* __restrict__ qV, const float* __restrict__ kV,
        const float* __restrict__ vV, const float* __restrict__ qb,
        const float* __restrict__ kb, const float* __restrict__ vb,
        __half* __restrict__ Qo, __half* __restrict__ Ko,
        __half* __restrict__ Vo) {
    GDC_WAIT();
    int which = blockIdx.z;
    const float* Vh = (which == 0) ? qV : (which == 1) ? kV : vV;
    const float* bias = (which == 0) ? qb : (which == 1) ? kb : vb;
    __half* out = (which == 0) ? Qo : (which == 1) ? Ko : Vo;
    float oscale = (which == 0) ? QSCALE : 1.0f;

    int bh = blockIdx.y;
    int b  = bh >> 4;
    int h  = bh & 15;
    int s0 = blockIdx.x * 256;

    __shared__ float Vs[RA][DHD];         // 8 KB
    __shared__ __half Xs[2][64][40];      // 2 x 5120 B (raw fp16, padded rows)

    int tid = threadIdx.x;
    int lane = tid & 31, w = tid >> 5;

    const float4* vp4 = (const float4*)(Vh + (size_t)h * RA * DHD);
    ((float4*)Vs)[tid]       = vp4[tid];
    ((float4*)Vs)[tid + 256] = vp4[tid + 256];

    size_t xbase = (size_t)(b * SS + s0) * HR3 + (size_t)which * HR + h * RA;
    int xrow = tid >> 2, xq = tid & 3;

    uint4 xv = *(const uint4*)(Xr + xbase + (size_t)xrow * HR3 + xq * 8);
    *(uint4*)&Xs[0][xrow][xq * 8] = xv;
    __syncthreads();

    int e2 = lane * 2;
    __half2 vcolA[RA/2], vcolB[RA/2];
    #pragma unroll
    for (int r = 0; r < RA/2; r++) {
        vcolA[r] = __floats2half2_rn(Vs[2*r][e2],     Vs[2*r+1][e2]);
        vcolB[r] = __floats2half2_rn(Vs[2*r][e2 + 1], Vs[2*r+1][e2 + 1]);
    }
    float bb0 = bias[h * DHD + e2];
    float bb1 = bias[h * DHD + e2 + 1];

    #pragma unroll
    for (int t = 0; t < 4; t++) {
        if (t < 3)
            xv = *(const uint4*)(Xr + xbase + (size_t)((t + 1) * 64 + xrow) * HR3 + xq * 8);
        #pragma unroll
        for (int k = 0; k < 8; k++) {
            int row = w + k * 8;
            const __half2* xp = (const __half2*)&Xs[t & 1][row][0];
            __half2 accA = __float2half2_rn(0.f);
            __half2 accB = __float2half2_rn(0.f);
            #pragma unroll
            for (int r = 0; r < RA/2; r++) {
                __half2 x2 = xp[r];
                accA = __hfma2(x2, vcolA[r], accA);
                accB = __hfma2(x2, vcolB[r], accB);
            }
            float a0 = (__low2float(accA) + __high2float(accA) + bb0) * oscale;
            float a1 = (__low2float(accB) + __high2float(accB) + bb1) * oscale;
            size_t oidx = ((size_t)bh * SS + s0 + t * 64 + row) * DHD + e2;
            *(uint32_t*)(out + oidx) = packh(a0, a1);
        }
        if (t < 3) {
            __syncthreads();
            *(uint4*)&Xs[(t + 1) & 1][xrow][xq * 8] = xv;
            __syncthreads();
        }
    }
}

// flash attention: paired complementary Q-tiles, fixed-shift exp2 softmax
#define FA_SMEM ((128*72 + 3*2*64*72) * 2)
__global__ void __launch_bounds__(256, 2)
flash_mma(const __half* __restrict__ Qg_, const __half* __restrict__ Kg_,
          const __half* __restrict__ Vg_, __half* __restrict__ O16) {
    GDC_WAIT();
    extern __shared__ char fsm[];
    uint32_t sQ = smem_u32(fsm);
    uint32_t sKV = sQ + 128*72*2;
    const uint32_t VOFF = 64*72*2;
    const uint32_t STGB = 2*VOFF;
    int bh = blockIdx.y;
    int b = bh >> 4, h = bh & 15;
    int tid = threadIdx.x, wid = tid >> 5, lane = tid & 31;
    int g = lane >> 2, i4 = lane & 3;
    const __half* Kg = Kg_ + (size_t)bh * SS * DHD;
    const __half* Vg = Vg_ + (size_t)bh * SS * DHD;
    int kbrow = (lane & 7) + ((lane >> 4) << 3);
    int kbcol = ((lane >> 3) & 1) * 8;
    int ntile = (int)gridDim.x * 2;

    #pragma unroll
    for (int half = 0; half < 2; half++) {
        int tileIdx = half ? (int)blockIdx.x : (ntile - 1 - (int)blockIdx.x);
        int m0 = tileIdx * 128;
        const __half* Qg = Qg_ + ((size_t)bh * SS + m0) * DHD;
        int NT = m0/64 + 2;

        if (half) __syncthreads();

        #pragma unroll
        for (int it = 0; it < 4; it++) {
            int i = tid + it * 256; int r = i >> 3, q = i & 7;
            cpa16(sQ + (uint32_t)(r*72 + q*8)*2, Qg + (size_t)r*DHD + q*8);
        }
        #pragma unroll
        for (int it = 0; it < 2; it++) {
            int i = tid + it * 256; int r = i >> 3, q = i & 7;
            uint32_t so = (uint32_t)(r*72 + q*8)*2;
            cpa16(sKV + so,        Kg + (size_t)r*DHD + q*8);
            cpa16(sKV + VOFF + so, Vg + (size_t)r*DHD + q*8);
        }
        CP_COMMIT();
        {
            const __half* Kp = Kg + (size_t)64*DHD;
            const __half* Vp = Vg + (size_t)64*DHD;
            #pragma unroll
            for (int it = 0; it < 2; it++) {
                int i = tid + it * 256; int r = i >> 3, q = i & 7;
                uint32_t so = (uint32_t)(r*72 + q*8)*2;
                cpa16(sKV + STGB + so,        Kp + (size_t)r*DHD + q*8);
                cpa16(sKV + STGB + VOFF + so, Vp + (size_t)r*DHD + q*8);
            }
            CP_COMMIT();
        }
        CP_WAIT(1);
        __syncthreads();

        uint32_t qf[4][4];
        {
            uint32_t base = sQ + (uint32_t)((wid*16 + (lane & 15))*72 + (lane >> 4)*8)*2;
            #pragma unroll
            for (int t = 0; t < 4; t++)
                ldmx4(qf[t][0], qf[t][1], qf[t][2], qf[t][3], base + (uint32_t)(t*16)*2);
        }

        float o[8][4];
        #pragma unroll
        for (int u = 0; u < 8; u++) { o[u][0]=o[u][1]=o[u][2]=o[u][3]=0.f; }
        float l0f = 0.f, l1f = 0.f;

        for (int ti = 0; ti < NT; ti++) {
            if (ti > 0) {
                if (ti + 1 < NT) { CP_WAIT(1); } else { CP_WAIT(0); }
                __syncthreads();
            }
            if (ti + 2 < NT) {
                const __half* Kp = Kg + (size_t)(ti+2)*64*DHD;
                const __half* Vp = Vg + (size_t)(ti+2)*64*DHD;
                uint32_t sst = sKV + (uint32_t)((ti+2) % 3) * STGB;
                #pragma unroll
                for (int it = 0; it < 2; it++) {
                    int i = tid + it * 256; int r = i >> 3, q = i & 7;
                    uint32_t so = (uint32_t)(r*72 + q*8)*2;
                    cpa16(sst + so,        Kp + (size_t)r*DHD + q*8);
                    cpa16(sst + VOFF + so, Vp + (size_t)r*DHD + q*8);
                }
                CP_COMMIT();
            }
            uint32_t sK = sKV + (uint32_t)(ti % 3) * STGB;
            uint32_t sV = sK + VOFF;

            float s[8][4];
            #pragma unroll
            for (int nt = 0; nt < 8; nt++) { s[nt][0]=s[nt][1]=s[nt][2]=s[nt][3]=0.f; }
            #pragma unroll
            for (int t = 0; t < 4; t++) {
                #pragma unroll
                for (int nip = 0; nip < 4; nip++) {
                    uint32_t addr = sK + (uint32_t)((nip*16 + kbrow)*72 + t*16 + kbcol)*2;
                    uint32_t b0, b1, b2, b3;
                    ldmx4(b0, b1, b2, b3, addr);
                    mma16816(s[2*nip],   qf[t][0], qf[t][1], qf[t][2], qf[t][3], b0, b1);
                    mma16816(s[2*nip+1], qf[t][0], qf[t][1], qf[t][2], qf[t][3], b2, b3);
                }
            }

            bool diag = (ti >= NT - 2);
            if (diag) {
                int grow0 = m0 + wid*16 + g;
                int grow1 = grow0 + 8;
                #pragma unroll
                for (int nt = 0; nt < 8; nt++) {
                    int c0 = ti*64 + nt*8 + 2*i4;
                    if (c0     > grow0) s[nt][0] = -1e30f;
                    if (c0 + 1 > grow0) s[nt][1] = -1e30f;
                    if (c0     > grow1) s[nt][2] = -1e30f;
                    if (c0 + 1 > grow1) s[nt][3] = -1e30f;
                }
            }
            #pragma unroll
            for (int nt = 0; nt < 8; nt++) {
                float p0 = ex2(s[nt][0]);
                float p1 = ex2(s[nt][1]);
                float p2 = ex2(s[nt][2]);
                float p3 = ex2(s[nt][3]);
                s[nt][0]=p0; s[nt][1]=p1; s[nt][2]=p2; s[nt][3]=p3;
                l0f += p0 + p1; l1f += p2 + p3;
            }

            #pragma unroll
            for (int t = 0; t < 4; t++) {
                uint32_t pa0 = packh(s[2*t][0],   s[2*t][1]);
                uint32_t pa1 = packh(s[2*t][2],   s[2*t][3]);
                uint32_t pa2 = packh(s[2*t+1][0], s[2*t+1][1]);
                uint32_t pa3 = packh(s[2*t+1][2], s[2*t+1][3]);
                #pragma unroll
                for (int u = 0; u < 4; u++) {
                    uint32_t addr = sV + (uint32_t)((t*16 + (lane & 15))*36
                                                    + u*8 + ((lane >> 4) << 2))*4;
                    uint32_t r0, r1, r2, r3;
                    ldmx4t(r0, r1, r2, r3, addr);
                    mma16816(o[2*u],     pa0, pa1, pa2, pa3, r0, r1);
                    mma16816(o[2*u + 1], pa0, pa1, pa2, pa3, r2, r3);
                }
            }
        }

        l0f += __shfl_xor_sync(0xffffffffu, l0f, 1);
        l0f += __shfl_xor_sync(0xffffffffu, l0f, 2);
        l1f += __shfl_xor_sync(0xffffffffu, l1f, 1);
        l1f += __shfl_xor_sync(0xffffffffu, l1f, 2);

        float inv0 = 1.f / l0f, inv1 = 1.f / l1f;
        int r0g = m0 + wid*16 + g;
        size_t base0 = ((size_t)b * SS + r0g) * DD + h * DHD;
        size_t base1 = base0 + 8 * (size_t)DD;
        #pragma unroll
        for (int u = 0; u < 8; u++) {
            int col = u*8 + 2*i4;
            *(uint32_t*)(O16 + base0 + col) = packh(o[u][0]*inv0, o[u][1]*inv0);
            *(uint32_t*)(O16 + base1 + col) = packh(o[u][2]*inv1, o[u][3]*inv1);
        }
    }
}

template<typename F, typename... Args>
static inline void launch_pdl(F kern, dim3 grid, dim3 block, size_t smem, Args... args) {
    cudaLaunchConfig_t cfg = {};
    cfg.gridDim = grid;
    cfg.blockDim = block;
    cfg.dynamicSmemBytes = smem;
    cfg.stream = 0;
    cudaLaunchAttribute attr[1];
    attr[0].id = cudaLaunchAttributeProgrammaticStreamSerialization;
    attr[0].val.programmaticStreamSerializationAllowed = 1;
    cfg.attrs = attr;
    cfg.numAttrs = 1;
    cudaLaunchKernelEx(&cfg, kern, args...);
}

extern "C" void kernel_launch(void* const* d_in, const int* in_sizes, int n_in,
                              void* d_out, int out_size) {
    const float* hidden = (const float*)d_in[0];
    const float* ln1_g  = (const float*)d_in[1];
    const float* ln1_b  = (const float*)d_in[2];
    const float* ln2_g  = (const float*)d_in[3];
    const float* ln2_b  = (const float*)d_in[4];
    const float* q_U = (const float*)d_in[5];
    const float* q_V = (const float*)d_in[6];
    const float* q_b = (const float*)d_in[7];
    const float* k_U = (const float*)d_in[8];
    const float* k_V = (const float*)d_in[9];
    const float* k_b = (const float*)d_in[10];
    const float* v_U = (const float*)d_in[11];
    const float* v_V = (const float*)d_in[12];
    const float* v_b = (const float*)d_in[13];
    const float* out_U = (const float*)d_in[14];
    const float* out_V = (const float*)d_in[15];
    const float* out_b = (const float*)d_in[16];
    const float* fc1_U = (const float*)d_in[17];
    const float* fc1_V = (const float*)d_in[18];
    const float* fc1_b = (const float*)d_in[19];
    const float* fc2_U = (const float*)d_in[20];
    const float* fc2_V = (const float*)d_in[21];
    const float* fc2_b = (const float*)d_in[22];
    float* out = (float*)d_out;

    float* hb;
    __half *A16, *C16, *R16, *Q16, *K16, *V16;
    __half *Wqkv, *Wou, *Wov, *Wf1u, *Wf1v, *Wf2u, *Wf2v;
    cudaGetSymbolAddress((void**)&hb,   g_h);
    cudaGetSymbolAddress((void**)&A16,  g_A16);
    cudaGetSymbolAddress((void**)&C16,  g_C16);
    cudaGetSymbolAddress((void**)&R16,  g_R16);
    cudaGetSymbolAddress((void**)&Q16,  g_Q16);
    cudaGetSymbolAddress((void**)&K16,  g_K16);
    cudaGetSymbolAddress((void**)&V16,  g_V16);
    cudaGetSymbolAddress((void**)&Wqkv, g_Wqkv);
    cudaGetSymbolAddress((void**)&Wou,  g_Wou);
    cudaGetSymbolAddress((void**)&Wov,  g_Wov);
    cudaGetSymbolAddress((void**)&Wf1u, g_Wf1u);
    cudaGetSymbolAddress((void**)&Wf1v, g_Wf1v);
    cudaGetSymbolAddress((void**)&Wf2u, g_Wf2u);
    cudaGetSymbolAddress((void**)&Wf2v, g_Wf2v);

    cudaFuncSetAttribute(gemm_mma<0,1>, cudaFuncAttributeMaxDynamicSharedMemorySize, GM_SMEM);
    cudaFuncSetAttribute(gemm_mma<1,0>, cudaFuncAttributeMaxDynamicSharedMemorySize, GM_SMEM);
    cudaFuncSetAttribute(gemm_mma<2,1>, cudaFuncAttributeMaxDynamicSharedMemorySize, GM_SMEM);
    cudaFuncSetAttribute(gemm_mma64<1>, cudaFuncAttributeMaxDynamicSharedMemorySize, GM64_SMEM);
    cudaFuncSetAttribute(flash_mma, cudaFuncAttributeMaxDynamicSharedMemorySize, FA_SMEM);

    launch_pdl(convAll, dim3(7680 + NROW), dim3(32, 8), (size_t)0,
               q_U, k_U, v_U, out_U, out_V, fc1_U, fc1_V, fc2_U, fc2_V,
               Wqkv, Wou, Wov, Wf1u, Wf1v, Wf2u, Wf2v, hidden, A16, ln1_g, ln1_b);

    launch_pdl(gemm_mma<0,1>, dim3(HR3/128, NROW/128), dim3(256), (size_t)GM_SMEM,
               (const __half*)A16, (const __half*)Wqkv, (float*)nullptr, R16,
               (const float*)nullptr, (const float*)nullptr, NROW, HR3, DD);

    launch_pdl(expand3, dim3(SS/256, BB*HH, 3), dim3(256), (size_t)0,
               (const __half*)R16, q_V, k_V, v_V, q_b, k_b, v_b, Q16, K16, V16);

    launch_pdl(flash_mma, dim3(SS/256, BB*HH), dim3(256), (size_t)FA_SMEM,
               (const __half*)Q16, (const __half*)K16, (const __half*)V16, C16);

    launch_pdl(gemm_mma64<1>, dim3(R_OUT/64, NROW/128), dim3(256), (size_t)GM64_SMEM,
               (const __half*)C16, (const __half*)Wou, (float*)nullptr, A16,
               NROW, R_OUT, DD);
    launch_pdl(gemm_mma<1,0>, dim3(DD/128, NROW/128), dim3(256), (size_t)GM_SMEM,
               (const __half*)A16, (const __half*)Wov, hb, (__half*)nullptr,
               out_b, hidden, NROW, DD, R_OUT);

    launch_pdl(ln_half, dim3(NROW), dim3(256), (size_t)0,
               (const float*)hb, C16, ln2_g, ln2_b);

    launch_pdl(gemm_mma64<1>, dim3(R_FC/64, NROW/128), dim3(256), (size_t)GM64_SMEM,
               (const __half*)C16, (const __half*)Wf1u, (float*)nullptr, A16,
               NROW, R_FC, DD);
    launch_pdl(gemm_mma<2,1>, dim3(II/128, NROW/128), dim3(256), (size_t)GM_SMEM,
               (const __half*)A16, (const __half*)Wf1v, (float*)nullptr, C16,
               fc1_b, (const float*)nullptr, NROW, II, R_FC);
    launch_pdl(gemm_mma64<1>, dim3(R_FC/64, NROW/128), dim3(256), (size_t)GM64_SMEM,
               (const __half*)C16, (const __half*)Wf2u, (float*)nullptr, A16,
               NROW, R_FC, II);
    launch_pdl(gemm_mma<1,0>, dim3(DD/128, NROW/128), dim3(256), (size_t)GM_SMEM,
               (const __half*)A16, (const __half*)Wf2v, out, (__half*)nullptr,
               fc2_b, hb, NROW, DD, R_FC);
}